// round 17
// baseline (speedup 1.0000x reference)
#include <cuda_runtime.h>
#include <cuda_fp16.h>

#define D        64
#define MAXN     100352           // padded to multiple of 1024 (scan chunks)
#define MAXE     1000000
#define CHUNK    1024
#define BN       128              // nodes per sage tile
#define PAH      136              // smem pitch for fp16 A'/W' tiles (halves): 272B rows
#define PB       68               // pool staging pitch (floats)

#define ABUF_HALVES (BN * PAH)            // 17408 halves = 34816 B
#define WBUF_HALVES (64 * PAH)            // 8704 halves  = 17408 B

static __device__ __forceinline__ unsigned pack_h2(float a, float b) {
    __half2 h = __floats2half2_rn(a, b);
    return *reinterpret_cast<unsigned*>(&h);
}
static __device__ __forceinline__ void ldsm4(unsigned* r, unsigned addr) {
    asm volatile("ldmatrix.sync.aligned.m8n8.x4.shared.b16 {%0,%1,%2,%3}, [%4];"
                 : "=r"(r[0]), "=r"(r[1]), "=r"(r[2]), "=r"(r[3]) : "r"(addr));
}
static __device__ __forceinline__ void mma16816(float* c, const unsigned* a,
                                                unsigned b0, unsigned b1) {
    asm volatile("mma.sync.aligned.m16n8k16.row.col.f32.f16.f16.f32 "
                 "{%0,%1,%2,%3}, {%4,%5,%6,%7}, {%8,%9}, {%0,%1,%2,%3};"
                 : "+f"(c[0]), "+f"(c[1]), "+f"(c[2]), "+f"(c[3])
                 : "r"(a[0]), "r"(a[1]), "r"(a[2]), "r"(a[3]), "r"(b0), "r"(b1));
}
// cp.async 16B with zero-fill when src_size==0.
static __device__ __forceinline__ void cpa16(unsigned saddr, const void* gptr, int src_size) {
    asm volatile("cp.async.ca.shared.global [%0], [%1], 16, %2;"
                 :: "r"(saddr), "l"(gptr), "r"(src_size));
}
static __device__ __forceinline__ void cpa_commit() {
    asm volatile("cp.async.commit_group;");
}
static __device__ __forceinline__ void cpa_wait0() {
    asm volatile("cp.async.wait_group 0;" ::: "memory");
}
static __device__ __forceinline__ void cpa_wait1() {
    asm volatile("cp.async.wait_group 1;" ::: "memory");
}

// Static device scratch.
__device__ __half g_mean16[(size_t)MAXN * D];  // pre-scaled mean (fp16)
__device__ __half g_x16[(size_t)MAXN * D];
__device__ __half g_h16[(size_t)MAXN * D];
__device__ __half g_w1[64 * 128];              // pre-converted [Wl|Wr] layer 1, [j][128]
__device__ __half g_w2[64 * 128];              // layer 2
__device__ int    g_cnt[MAXN];
__device__ int    g_off[MAXN];
__device__ int    g_srcs[MAXE];
__device__ int    g_chunksum[128];
__device__ int    g_chunkbase[128];
__device__ int    g_done;
__device__ float  g_rbc[64];       // 1/max(count(batch==b),1)

// ---------------------------------------------------------------------------
// k0: zero histogram/flags/pool output, pre-convert W1/W2 to fp16, rbc.
// ---------------------------------------------------------------------------
__global__ __launch_bounds__(256) void zero_kernel(int n_pad, float* __restrict__ out,
                                                   int n_out, const int* __restrict__ batch,
                                                   int N,
                                                   const float4* __restrict__ W1l4,
                                                   const float4* __restrict__ W1r4,
                                                   const float4* __restrict__ W2l4,
                                                   const float4* __restrict__ W2r4) {
    int i = blockIdx.x * 256 + threadIdx.x;
    if (i < n_pad) g_cnt[i] = 0;
    if (i < n_out) out[i] = 0.f;
    if (i == 0) g_done = 0;
    if (i < 4096) {
        int layer = i >> 11;            // 0: W1, 1: W2
        int ii = i & 2047;
        int half2nd = (ii >= 1024);
        int jj = ii & 1023;
        int j = jj >> 4, kq = jj & 15;  // row j, float4 index kq
        const float4* srcm = layer ? (half2nd ? W2r4 : W2l4)
                                   : (half2nd ? W1r4 : W1l4);
        float4 v = __ldg(&srcm[j * 16 + kq]);
        uint2 p;
        p.x = pack_h2(v.x, v.y);
        p.y = pack_h2(v.z, v.w);
        __half* dst = layer ? g_w2 : g_w1;
        *reinterpret_cast<uint2*>(&dst[j * 128 + half2nd * 64 + kq * 4]) = p;
    }
    if (blockIdx.x == 0 && threadIdx.x < 64) {
        int b = threadIdx.x;
        int lo0 = 0, hi = N;
        while (lo0 < hi) { int mid = (lo0 + hi) >> 1; if (__ldg(&batch[mid]) < b) lo0 = mid + 1; else hi = mid; }
        int lo1 = lo0; hi = N;
        while (lo1 < hi) { int mid = (lo1 + hi) >> 1; if (__ldg(&batch[mid]) < b + 1) lo1 = mid + 1; else hi = mid; }
        g_rbc[b] = 1.0f / fmaxf((float)(lo1 - lo0), 1.0f);
    }
}

// ---------------------------------------------------------------------------
// k1: in-degree histogram over dst (int4 loads) FUSED with x -> fp16 convert.
// ---------------------------------------------------------------------------
__global__ __launch_bounds__(256) void hist_conv_kernel(const int* __restrict__ dst, int E,
                                                        const float4* __restrict__ x4,
                                                        int n4) {
    int i = blockIdx.x * 256 + threadIdx.x;
    int hq = (E + 3) >> 2;
    if (i < hq) {
        int e = i * 4;
        if (e + 4 <= E) {
            int4 d = __ldg(reinterpret_cast<const int4*>(dst) + i);
            atomicAdd(&g_cnt[d.x], 1);
            atomicAdd(&g_cnt[d.y], 1);
            atomicAdd(&g_cnt[d.z], 1);
            atomicAdd(&g_cnt[d.w], 1);
        } else {
            for (; e < E; e++) atomicAdd(&g_cnt[__ldg(&dst[e])], 1);
        }
    }
    if (i < n4) {
        float4 v = __ldg(&x4[i]);
        uint2 p;
        p.x = pack_h2(v.x, v.y);
        p.y = pack_h2(v.z, v.w);
        reinterpret_cast<uint2*>(g_x16)[i] = p;
    }
}

// ---------------------------------------------------------------------------
// k2: per-chunk (1024) exclusive scan of g_cnt -> g_off (chunk-local); last
// block scans the chunk totals into g_chunkbase (decoupled via g_done).
// ---------------------------------------------------------------------------
__global__ __launch_bounds__(256) void scan_chunk_kernel() {
    __shared__ int w[256];
    __shared__ int isLast;
    int t = threadIdx.x;
    int base = blockIdx.x * CHUNK + t * 4;
    int4 c = *reinterpret_cast<const int4*>(&g_cnt[base]);
    int s0 = c.x, s1 = s0 + c.y, s2 = s1 + c.z, s3 = s2 + c.w;
    w[t] = s3;
    __syncthreads();
#pragma unroll
    for (int off = 1; off < 256; off <<= 1) {
        int v = (t >= off) ? w[t - off] : 0;
        __syncthreads();
        w[t] += v;
        __syncthreads();
    }
    int excl = (t > 0) ? w[t - 1] : 0;
    int4 o;
    o.x = excl; o.y = excl + s0; o.z = excl + s1; o.w = excl + s2;
    *reinterpret_cast<int4*>(&g_off[base]) = o;
    if (t == 255) g_chunksum[blockIdx.x] = w[255];

    __threadfence();
    if (t == 0) isLast = (atomicAdd(&g_done, 1) == (int)gridDim.x - 1);
    __syncthreads();
    if (isLast) {
        int v = 0;
        if (t < 128 && t < (int)gridDim.x)
            v = *((volatile int*)&g_chunksum[t]);
        if (t < 128) w[t] = v;
        __syncthreads();
#pragma unroll
        for (int off = 1; off < 128; off <<= 1) {
            int u = 0;
            if (t < 128 && t >= off) u = w[t - off];
            __syncthreads();
            if (t < 128) w[t] += u;
            __syncthreads();
        }
        if (t < 128) g_chunkbase[t] = (t > 0) ? w[t - 1] : 0;
    }
}

// ---------------------------------------------------------------------------
// k3: fill dst-sorted src list (scalar; latency-bound, max occupancy).
// ---------------------------------------------------------------------------
__global__ __launch_bounds__(256) void fill_kernel(const int* __restrict__ src,
                                                   const int* __restrict__ dst, int E) {
    int e = blockIdx.x * 256 + threadIdx.x;
    if (e >= E) return;
    int d = __ldg(&dst[e]);
    int p = atomicAdd(&g_off[d], 1) + __ldg(&g_chunkbase[d >> 10]);
    g_srcs[p] = __ldg(&src[e]);
}

// ---------------------------------------------------------------------------
// Gather aggregation (fp16 payload): 8 threads per dst node, shuffle-broadcast
// edge indices, fp32 accumulation, writes PRE-SCALED fp16 mean.
// ---------------------------------------------------------------------------
__global__ __launch_bounds__(256) void agg_kernel(const __half* __restrict__ feat, int N) {
    int g = blockIdx.x * 32 + (threadIdx.x >> 3);
    int lane = threadIdx.x & 7;
    unsigned gmask = 0xFFu << ((threadIdx.x & 31) & ~7);
    bool active = (g < N);
    int cnt = active ? g_cnt[g] : 0;
    int start = active ? (g_off[g] + __ldg(&g_chunkbase[g >> 10]) - cnt) : 0;
    const uint4* f4 = reinterpret_cast<const uint4*>(feat);
    float a[8];
#pragma unroll
    for (int c = 0; c < 8; c++) a[c] = 0.f;

    for (int i = 0; i < cnt; i += 8) {
        int my = (i + lane < cnt) ? __ldg(&g_srcs[start + i + lane]) : 0;
        int lim = cnt - i;
#pragma unroll
        for (int e = 0; e < 8; e++) {
            if (e >= lim) break;
            int s = __shfl_sync(gmask, my, e, 8);
            uint4 v = __ldg(f4 + (size_t)s * 8 + lane);
            float2 f0 = __half22float2(*reinterpret_cast<__half2*>(&v.x));
            float2 f1 = __half22float2(*reinterpret_cast<__half2*>(&v.y));
            float2 f2 = __half22float2(*reinterpret_cast<__half2*>(&v.z));
            float2 f3 = __half22float2(*reinterpret_cast<__half2*>(&v.w));
            a[0] += f0.x; a[1] += f0.y; a[2] += f1.x; a[3] += f1.y;
            a[4] += f2.x; a[5] += f2.y; a[6] += f3.x; a[7] += f3.y;
        }
    }
    if (active) {
        float r = 1.0f / fmaxf((float)cnt, 1.0f);
        uint4 pk;
        pk.x = pack_h2(a[0] * r, a[1] * r);
        pk.y = pack_h2(a[2] * r, a[3] * r);
        pk.z = pack_h2(a[4] * r, a[5] * r);
        pk.w = pack_h2(a[6] * r, a[7] * r);
        reinterpret_cast<uint4*>(g_mean16)[(size_t)g * 8 + lane] = pk;
    }
}

// ---------------------------------------------------------------------------
// Persistent double-buffered tensor-core SAGE layer.
// Each block loops over tiles; W staged once; next tile's A prefetched via
// cp.async while the current tile computes (wait_group 1 pipeline).
// ---------------------------------------------------------------------------
__global__ __launch_bounds__(256) void sage_kernel(const __half* __restrict__ xin16,
                                                   const __half* __restrict__ Wc,
                                                   const float* __restrict__ bl,
                                                   __half* __restrict__ hout16,
                                                   const int* __restrict__ batch,
                                                   float* __restrict__ pool_out,
                                                   int N, int do_pool, int T) {
    extern __shared__ char smraw[];
    __half* sA0  = reinterpret_cast<__half*>(smraw);                 // BN x PAH
    __half* sA1  = sA0 + ABUF_HALVES;                                // BN x PAH
    __half* sW   = sA1 + ABUF_HALVES;                                // 64 x PAH
    float*  sRbc = reinterpret_cast<float*>(sW + WBUF_HALVES);       // 64
    int*    sBat = reinterpret_cast<int*>(sRbc + 64);                // 128

    const int tid = threadIdx.x;
    const int NB  = gridDim.x;
    const int t0  = blockIdx.x;
    if (t0 >= T) return;

    unsigned sAb[2];
    sAb[0] = (unsigned)__cvta_generic_to_shared(sA0);
    sAb[1] = (unsigned)__cvta_generic_to_shared(sA1);
    unsigned sWb = (unsigned)__cvta_generic_to_shared(sW);

    const int l  = tid & 31;
    const int w  = tid >> 5;
    const int m0 = w * 16;
    const unsigned aOff = (unsigned)((m0 + (l & 15)) * (PAH * 2) + (l >> 4) * 16);
    const unsigned bAddr = sWb + (unsigned)((((l & 7) + ((l >> 4) << 3)) * (PAH * 2)) + ((l >> 3) & 1) * 16);
    const int c2 = (l & 3) * 2;
    const int r0 = m0 + (l >> 2);
    const int r1 = r0 + 8;

    // Stage A tile for `tile` into buffer base address ab (2048 x 16B chunks).
    auto stageA = [&](int tile, unsigned ab) {
        const int base = tile * BN;
#pragma unroll
        for (int r = 0; r < 8; r++) {
            int i = r * 256 + tid;
            int half2nd = (i >= BN * 8);
            int ii = i - half2nd * BN * 8;
            int n = ii >> 3, q = ii & 7;
            int node = base + n;
            const __half* srcbuf = half2nd ? xin16 : g_mean16;
            const void* gp = srcbuf + ((size_t)(node < N ? node : 0) * 64 + q * 8);
            cpa16(ab + (unsigned)((n * PAH + half2nd * 64 + q * 8) * 2), gp,
                  (node < N) ? 16 : 0);
        }
    };

    // Pre-loop: stage W (once) + A(t0) as group 0.
#pragma unroll
    for (int r = 0; r < 4; r++) {
        int c = r * 256 + tid;
        int j = c >> 4, q = c & 15;
        cpa16(sWb + (unsigned)((j * PAH + q * 8) * 2), Wc + j * 128 + q * 8, 16);
    }
    stageA(t0, sAb[0]);
    cpa_commit();

    if (do_pool && tid >= BN && tid < BN + 64) sRbc[tid - BN] = g_rbc[tid - BN];

    int buf = 0;
    for (int t = t0; t < T; t += NB, buf ^= 1) {
        const int base = t * BN;
        const int nxt = t + NB;
        if (nxt < T) {
            stageA(nxt, sAb[buf ^ 1]);
            cpa_commit();
            cpa_wait1();          // A(t) complete; A(nxt) may stay in flight
        } else {
            cpa_wait0();
        }
        __syncthreads();          // staged data visible to all threads

        if (do_pool && tid < BN) {
            int node = base + tid;
            sBat[tid] = (node < N) ? __ldg(&batch[node]) : 0;
        }

        const unsigned aAddr = sAb[buf] + aOff;
        float acc[8][4];
#pragma unroll
        for (int nt = 0; nt < 8; nt++)
#pragma unroll
            for (int c = 0; c < 4; c++) acc[nt][c] = 0.f;

#pragma unroll
        for (int ks = 0; ks < 8; ks++) {
            unsigned a[4];
            ldsm4(a, aAddr + ks * 32);
#pragma unroll
            for (int np = 0; np < 4; np++) {
                unsigned tt[4];
                ldsm4(tt, bAddr + np * (16 * PAH * 2) + ks * 32);
                mma16816(acc[2 * np],     a, tt[0], tt[1]);
                mma16816(acc[2 * np + 1], a, tt[2], tt[3]);
            }
        }

        __half* sAcur = buf ? sA1 : sA0;
        if (!do_pool) {
            // Smem-transposed epilogue in the CURRENT buffer, then coalesced stores.
            __syncthreads();  // all ldsm of current buffer retired
#pragma unroll
            for (int nt = 0; nt < 8; nt++) {
                int col = nt * 8 + c2;
                float b0 = __ldg(&bl[col]), b1 = __ldg(&bl[col + 1]);
                *reinterpret_cast<unsigned*>(&sAcur[r0 * PAH + col]) =
                    pack_h2(fmaxf(acc[nt][0] + b0, 0.f), fmaxf(acc[nt][1] + b1, 0.f));
                *reinterpret_cast<unsigned*>(&sAcur[r1 * PAH + col]) =
                    pack_h2(fmaxf(acc[nt][2] + b0, 0.f), fmaxf(acc[nt][3] + b1, 0.f));
            }
            __syncthreads();
#pragma unroll
            for (int r = 0; r < 4; r++) {
                int i = r * 256 + tid;
                int n = i >> 3, q = i & 7;
                int node = base + n;
                if (node < N) {
                    uint4 v = *reinterpret_cast<const uint4*>(&sAcur[n * PAH + q * 8]);
                    reinterpret_cast<uint4*>(hout16)[(size_t)node * 8 + q] = v;
                }
            }
        } else {
            float* pb = reinterpret_cast<float*>(sAcur);   // 128 x PB floats = buffer size
            __syncthreads();  // done reading current buffer via ldsm
#pragma unroll
            for (int nt = 0; nt < 8; nt++) {
                int col = nt * 8 + c2;
                float b0 = __ldg(&bl[col]), b1 = __ldg(&bl[col + 1]);
                float2 v0, v1;
                v0.x = (base + r0 < N) ? acc[nt][0] + b0 : 0.f;
                v0.y = (base + r0 < N) ? acc[nt][1] + b1 : 0.f;
                v1.x = (base + r1 < N) ? acc[nt][2] + b0 : 0.f;
                v1.y = (base + r1 < N) ? acc[nt][3] + b1 : 0.f;
                *reinterpret_cast<float2*>(&pb[r0 * PB + col]) = v0;
                *reinterpret_cast<float2*>(&pb[r1 * PB + col]) = v1;
            }
            __syncthreads();
            if (tid < 64) {
                const int j = tid;
                int cur = sBat[0];
                float sum = 0.f;
#pragma unroll 4
                for (int n = 0; n < BN; n++) {
                    int b = sBat[n];
                    if (b != cur) {
                        atomicAdd(&pool_out[cur * 64 + j], sum * sRbc[cur]);
                        sum = 0.f;
                        cur = b;
                    }
                    sum += pb[n * PB + j];
                }
                atomicAdd(&pool_out[cur * 64 + j], sum * sRbc[cur]);
            }
        }
        __syncthreads();   // epilogue reads done before next prefetch overwrites
    }
}

// ---------------------------------------------------------------------------
// kernel_launch
// Inputs: x, edge_index, edge_attr, batch, edge_emb,
//         W1_l, b1_l, W1_r, W2_l, b2_l, W2_r
// ---------------------------------------------------------------------------
extern "C" void kernel_launch(void* const* d_in, const int* in_sizes, int n_in,
                              void* d_out, int out_size) {
    const float* x     = (const float*)d_in[0];
    const int*   eidx  = (const int*)d_in[1];
    const int*   batch = (const int*)d_in[3];
    const float* W1l   = (const float*)d_in[5];
    const float* b1l   = (const float*)d_in[6];
    const float* W1r   = (const float*)d_in[7];
    const float* W2l   = (const float*)d_in[8];
    const float* b2l   = (const float*)d_in[9];
    const float* W2r   = (const float*)d_in[10];
    float*       out   = (float*)d_out;

    const int N = in_sizes[3];
    const int E = in_sizes[1] / 2;
    const int* src = eidx;
    const int* dst = eidx + E;

    void* xp = nullptr; void* hp = nullptr; void* w1p = nullptr; void* w2p = nullptr;
    cudaGetSymbolAddress(&xp, g_x16);
    cudaGetSymbolAddress(&hp, g_h16);
    cudaGetSymbolAddress(&w1p, g_w1);
    cudaGetSymbolAddress(&w2p, g_w2);
    __half* x16 = (__half*)xp;
    __half* h16 = (__half*)hp;
    __half* w1c = (__half*)w1p;
    __half* w2c = (__half*)w2p;

    const int smem = (2 * ABUF_HALVES + WBUF_HALVES) * (int)sizeof(__half)
                     + 64 * (int)sizeof(float) + BN * (int)sizeof(int);   // ~88 KB
    cudaFuncSetAttribute(sage_kernel, cudaFuncAttributeMaxDynamicSharedMemorySize, smem);

    int nsm = 0;
    cudaDeviceGetAttribute(&nsm, cudaDevAttrMultiProcessorCount, 0);
    if (nsm <= 0) nsm = 148;
    int maxb = 0;
    cudaOccupancyMaxActiveBlocksPerMultiprocessor(&maxb, sage_kernel, 256, smem);
    if (maxb < 1) maxb = 1;

    const int nchunk = (N + CHUNK - 1) / CHUNK;
    const int n_pad  = nchunk * CHUNK;
    const int n4     = N * 16;
    const int zb     = (n_pad + 255) / 256;
    const int hq     = (E + 3) / 4;
    const int hcb    = (max(hq, n4) + 255) / 256;
    const int eblk   = (E + 255) / 256;
    const int ablk   = (N + 31) / 32;
    const int T      = (N + BN - 1) / BN;          // tiles
    const int gblk   = min(T, nsm * maxb);         // persistent grid

    // CSR build + conversions (once; reused by both layers)
    zero_kernel<<<zb, 256>>>(n_pad, out, out_size, batch, N,
                             reinterpret_cast<const float4*>(W1l),
                             reinterpret_cast<const float4*>(W1r),
                             reinterpret_cast<const float4*>(W2l),
                             reinterpret_cast<const float4*>(W2r));
    hist_conv_kernel<<<hcb, 256>>>(dst, E, reinterpret_cast<const float4*>(x), n4);
    scan_chunk_kernel<<<nchunk, 256>>>();
    fill_kernel<<<eblk, 256>>>(src, dst, E);

    // Layer 1
    agg_kernel<<<ablk, 256>>>(x16, N);
    sage_kernel<<<gblk, 256, smem>>>(x16, w1c, b1l, h16, nullptr, nullptr, N, 0, T);

    // Layer 2 + fused scaled pool
    agg_kernel<<<ablk, 256>>>(h16, N);
    sage_kernel<<<gblk, 256, smem>>>(h16, w2c, b2l, nullptr, batch, out, N, 1, T);
}